// round 15
// baseline (speedup 1.0000x reference)
#include <cuda_runtime.h>
#include <cstdint>
#include <cuda_fp16.h>
#include <mma.h>
#include <math.h>

using namespace nvcuda;

#define HH 512
#define SS 6
#define MAXB 16384
#define KC 576      // comb K: 512 attn_applied + input + bias + pad to 64
#define KG 1088     // gates K: 512 x + 512 hidden + bias + pad to 64

// ---- scratch (static device globals; no runtime allocation) ----
__device__ __align__(16) __half g_Xc  [(size_t)MAXB * KC];
__device__ __align__(16) __half g_Abig[(size_t)MAXB * KG];
__device__ __align__(16) __half g_Wc  [HH * KC];
__device__ __align__(16) __half g_Wg  [4 * HH * KG];   // rows interleaved: n' = 4*j + gate

__device__ __forceinline__ float sigm_fast(float x) {
    return __fdividef(1.f, 1.f + __expf(-x));
}
__device__ __forceinline__ float tanh_fast(float x) {
    return __fmaf_rn(2.f, sigm_fast(2.f * x), -1.f);
}

// ---- build padded weight matrices (fp16) ----
// g_Wg row n' = 4*j + g  maps to torch row  n_old = g*512 + j  (gate order i,f,g,o)
__global__ void init_weights(const float* __restrict__ Wcomb, const float* __restrict__ bcomb,
                             const float* __restrict__ Wih,   const float* __restrict__ Whh,
                             const float* __restrict__ bih,   const float* __restrict__ bhh) {
    int idx = blockIdx.x * blockDim.x + threadIdx.x;
    int stride = gridDim.x * blockDim.x;
    for (int i = idx; i < HH * KC; i += stride) {
        int n = i / KC, k = i % KC;
        float v = 0.f;
        if (k < 512)        v = Wcomb[n * 513 + 1 + k];
        else if (k == 512)  v = Wcomb[n * 513];
        else if (k == 513)  v = bcomb[n];
        g_Wc[i] = __float2half_rn(v);
    }
    for (int i = idx; i < 4 * HH * KG; i += stride) {
        int np = i / KG, k = i % KG;
        int j = np >> 2, g = np & 3;
        int n = g * 512 + j;               // torch gate-major row
        float v = 0.f;
        if (k < 512)        v = Wih[n * 512 + k];
        else if (k < 1024)  v = Whh[n * 512 + (k - 512)];
        else if (k == 1024) v = bih[n] + bhh[n];
        g_Wg[i] = __float2half_rn(v);
    }
}

// ---- attention (R11 version: 256 threads, best measured) ----
__global__ void attn_kernel(const float* __restrict__ input, const float* __restrict__ hidden,
                            const float* __restrict__ cell,  const float* __restrict__ enc,
                            const float* __restrict__ Wattn, const float* __restrict__ battn,
                            float* __restrict__ out_attnw) {
    int b = blockIdx.x;
    int tid = threadIdx.x;             // 256 threads
    __shared__ float s_w[SS];
    __shared__ float s_part[8][SS];

    float h0 = hidden[(size_t)b * HH + tid];
    float h1 = hidden[(size_t)b * HH + tid + 256];
    float c0 = cell  [(size_t)b * HH + tid];
    float c1 = cell  [(size_t)b * HH + tid + 256];

    float p[SS];
#pragma unroll
    for (int s = 0; s < SS; s++) {
        const float* wr = Wattn + s * 1025;
        p[s] = wr[1 + tid] * h0 + wr[1 + tid + 256] * h1
             + wr[513 + tid] * c0 + wr[513 + tid + 256] * c1;
    }
#pragma unroll
    for (int s = 0; s < SS; s++)
#pragma unroll
        for (int off = 16; off; off >>= 1)
            p[s] += __shfl_down_sync(0xffffffffu, p[s], off);
    int warp = tid >> 5, lane = tid & 31;
    if (lane == 0)
#pragma unroll
        for (int s = 0; s < SS; s++) s_part[warp][s] = p[s];
    __syncthreads();

    if (tid == 0) {
        float inp = input[b];
        float lg[SS], mx = -1e30f;
#pragma unroll
        for (int s = 0; s < SS; s++) {
            float v = battn[s] + Wattn[s * 1025] * inp;
#pragma unroll
            for (int w = 0; w < 8; w++) v += s_part[w][s];
            lg[s] = v; mx = fmaxf(mx, v);
        }
        float sum = 0.f;
#pragma unroll
        for (int s = 0; s < SS; s++) { lg[s] = __expf(lg[s] - mx); sum += lg[s]; }
        float inv = __fdividef(1.f, sum);
#pragma unroll
        for (int s = 0; s < SS; s++) {
            float w = lg[s] * inv;
            s_w[s] = w;
            out_attnw[(size_t)b * SS + s] = w;
        }
    }
    __syncthreads();

    float w0 = s_w[0], w1 = s_w[1], w2 = s_w[2], w3 = s_w[3], w4 = s_w[4], w5 = s_w[5];
    const float* eb = enc + (size_t)b * SS * HH;
#pragma unroll
    for (int r = 0; r < 2; r++) {
        int k = tid + r * 256;
        float a = w0 * eb[k]          + w1 * eb[HH + k]     + w2 * eb[2 * HH + k]
                + w3 * eb[3 * HH + k] + w4 * eb[4 * HH + k] + w5 * eb[5 * HH + k];
        g_Xc[(size_t)b * KC + k] = __float2half_rn(a);
        g_Abig[(size_t)b * KG + 512 + k] = __float2half_rn((r == 0) ? h0 : h1);
    }
    if (tid < 64) {
        float v = 0.f;
        if (tid == 0) v = input[b];
        else if (tid == 1) v = 1.f;
        g_Xc[(size_t)b * KC + 512 + tid] = __float2half_rn(v);
        float u = (tid == 0) ? 1.f : 0.f;
        g_Abig[(size_t)b * KG + 1024 + tid] = __float2half_rn(u);
    }
}

// ---- fp16 wmma GEMM, 64x128 CTA tile, 4 warps (32x64/warp), BK=32,
//      3-stage cp.async (wait_group 1), 4 CTAs/SM ----
// EPI 0: relu -> half C  (comb)   EPI 1: fused LSTM (gates; N interleaved 4*j+g)
#define CP16(dst_u32, src_ptr) \
    asm volatile("cp.async.cg.shared.global [%0], [%1], 16;" :: "r"(dst_u32), "l"(src_ptr))

template <int EPI>
__global__ void __launch_bounds__(128, 4)
gemm_fp16(const __half* __restrict__ A, int lda,
          const __half* __restrict__ Bw, int ldb,
          void* __restrict__ Cv, int ldc, int K,
          const float* __restrict__ cell,
          float* __restrict__ o_h, float* __restrict__ o_c) {
    constexpr int BM = 64, BN = 128, BK = 32, PAD = 40;   // PAD halves (80B rows)
    constexpr int NSTG = 3;
    constexpr int ASTG = BM * PAD;        // halves per A stage
    constexpr int BSTG = BN * PAD;
    extern __shared__ __half smem[];
    __half* As = smem;                    // NSTG * ASTG
    __half* Bs = smem + NSTG * ASTG;      // NSTG * BSTG

    int m0 = blockIdx.y * BM, n0 = blockIdx.x * BN;
    int tid = threadIdx.x;                // 128 threads = 4 warps
    int warp = tid >> 5, lane = tid & 31;
    int wr = warp & 1;    // 0..1 -> 32-row slab
    int wc = warp >> 1;   // 0..1 -> 64-col slab

    wmma::fragment<wmma::accumulator, 16, 16, 16, float> acc[2][4];
#pragma unroll
    for (int i = 0; i < 2; i++)
#pragma unroll
        for (int j = 0; j < 4; j++) wmma::fill_fragment(acc[i][j], 0.f);

    int nk = K / BK;                      // 18 (comb) or 34 (gates)

    // per stage: A 64 rows x 4 chunks(16B) = 256 ; B 128 x 4 = 512 chunks
    auto stage_copy = [&](int st, int k0) {
#pragma unroll
        for (int i = 0; i < 2; i++) {
            int q = tid + i * 128;
            int row = q >> 2, c8 = (q & 3) << 3;
            const __half* ga = &A[(size_t)(m0 + row) * lda + k0 + c8];
            unsigned int sa = (unsigned int)__cvta_generic_to_shared(&As[st * ASTG + row * PAD + c8]);
            CP16(sa, ga);
        }
#pragma unroll
        for (int i = 0; i < 4; i++) {
            int q = tid + i * 128;
            int row = q >> 2, c8 = (q & 3) << 3;
            const __half* gb = &Bw[(size_t)(n0 + row) * ldb + k0 + c8];
            unsigned int sb = (unsigned int)__cvta_generic_to_shared(&Bs[st * BSTG + row * PAD + c8]);
            CP16(sb, gb);
        }
        asm volatile("cp.async.commit_group;");
    };

    stage_copy(0, 0);
    stage_copy(1, BK);

    for (int t = 0; t < nk; t++) {
        // ensure stage t (oldest pending) has landed; allow stage t+1 in flight
        if (t + 1 < nk) asm volatile("cp.async.wait_group 1;");
        else            asm volatile("cp.async.wait_group 0;");
        __syncthreads();   // stage t visible to all; stage t-1 consumed by all
        if (t + 2 < nk) stage_copy((t + 2) % NSTG, (t + 2) * BK);

        const __half* Ab = &As[(t % NSTG) * ASTG];
        const __half* Bb = &Bs[(t % NSTG) * BSTG];

#pragma unroll
        for (int kk = 0; kk < 2; kk++) {     // 2 x k=16
            wmma::fragment<wmma::matrix_a, 16, 16, 16, __half, wmma::row_major> af[2];
            wmma::fragment<wmma::matrix_b, 16, 16, 16, __half, wmma::col_major> bf[4];
#pragma unroll
            for (int i = 0; i < 2; i++)
                wmma::load_matrix_sync(af[i], &Ab[(wr * 32 + i * 16) * PAD + kk * 16], PAD);
#pragma unroll
            for (int j = 0; j < 4; j++)
                wmma::load_matrix_sync(bf[j], &Bb[(wc * 64 + j * 16) * PAD + kk * 16], PAD);
#pragma unroll
            for (int i = 0; i < 2; i++)
#pragma unroll
                for (int j = 0; j < 4; j++)
                    wmma::mma_sync(acc[i][j], af[i], bf[j], acc[i][j]);
        }
    }

    // ---- epilogue: stage accumulators through smem (mainloop smem dead) ----
    __syncthreads();
    float* stg = (float*)smem;
    constexpr int LDS_ = 68;
    float* wbase = stg + warp * 32 * LDS_;   // 4 warps x 32x68 f32 = 34.8KB < 46KB
#pragma unroll
    for (int i = 0; i < 2; i++)
#pragma unroll
        for (int j = 0; j < 4; j++)
            wmma::store_matrix_sync(&wbase[(i * 16) * LDS_ + j * 16], acc[i][j],
                                    LDS_, wmma::mem_row_major);
    __syncwarp();

    if (EPI == 0) {
        __half* Ch = (__half*)Cv;
        {
            int r = lane;                 // 32 lanes cover the 32 rows
            size_t grow = (size_t)(m0 + wr * 32 + r) * ldc + n0 + wc * 64;
#pragma unroll
            for (int c = 0; c < 64; c += 2) {
                float x = fmaxf(wbase[r * LDS_ + c], 0.f);
                float y = fmaxf(wbase[r * LDS_ + c + 1], 0.f);
                *(__half2*)&Ch[grow + c] = __floats2half2_rn(x, y);
            }
        }
    } else {
        // fused LSTM: this warp's 64 cols = interleaved gates for 16 hidden units
        int nbase = n0 + wc * 64;
        int jbase = nbase >> 2;
#pragma unroll 4
        for (int it = 0; it < 16; it++) {
            int idx = it * 32 + lane;         // 0..511 over (row, jj)
            int r = idx >> 4, jj = idx & 15;
            int b = m0 + wr * 32 + r;
            int j = jbase + jj;
            const float* cellrow = &wbase[r * LDS_ + jj * 4];
            float gi = cellrow[0], gf = cellrow[1], gg = cellrow[2], go = cellrow[3];
            float c_old = cell[(size_t)b * HH + j];
            float si = sigm_fast(gi);
            float sf = sigm_fast(gf);
            float so = sigm_fast(go);
            float tg = tanh_fast(gg);
            float cn = sf * c_old + si * tg;
            float hn = so * tanh_fast(cn);
            o_c[(size_t)b * HH + j] = cn;
            o_h[(size_t)b * HH + j] = hn;
        }
    }
}

// ---- output dot: out[b] = dot(o_h[b,:], Wout) + bout ----
__global__ void dot_kernel(const float* __restrict__ o_h, const float* __restrict__ Wout,
                           const float* __restrict__ bout, float* __restrict__ out_output) {
    int b = blockIdx.x, j = threadIdx.x;   // 512 threads
    float part = o_h[(size_t)b * HH + j] * Wout[j];
#pragma unroll
    for (int off = 16; off; off >>= 1) part += __shfl_down_sync(0xffffffffu, part, off);
    __shared__ float sp[16];
    if ((j & 31) == 0) sp[j >> 5] = part;
    __syncthreads();
    if (j < 16) {
        float v = sp[j];
#pragma unroll
        for (int off = 8; off; off >>= 1) v += __shfl_down_sync(0xffffu, v, off);
        if (j == 0) out_output[b] = v + bout[0];
    }
}

extern "C" void kernel_launch(void* const* d_in, const int* in_sizes, int n_in,
                              void* d_out, int out_size) {
    const float* input  = (const float*)d_in[0];
    const float* hidden = (const float*)d_in[1];
    const float* cell   = (const float*)d_in[2];
    const float* enc    = (const float*)d_in[3];
    const float* Wattn  = (const float*)d_in[4];
    const float* battn  = (const float*)d_in[5];
    const float* Wcomb  = (const float*)d_in[6];
    const float* bcomb  = (const float*)d_in[7];
    const float* Wih    = (const float*)d_in[8];
    const float* Whh    = (const float*)d_in[9];
    const float* bih    = (const float*)d_in[10];
    const float* bhh    = (const float*)d_in[11];
    const float* Wout   = (const float*)d_in[12];
    const float* bout   = (const float*)d_in[13];

    int B = in_sizes[1] / HH;   // 16384

    float* out      = (float*)d_out;
    float* o_output = out;                              // [B, 1]
    float* o_h      = out + (size_t)B;                  // [B, H]
    float* o_c      = o_h + (size_t)B * HH;             // [B, H]
    float* o_aw     = o_c + (size_t)B * HH;             // [B, 1, S]

    __half *pXc, *pAbig, *pWc, *pWg;
    cudaGetSymbolAddress((void**)&pXc,    g_Xc);
    cudaGetSymbolAddress((void**)&pAbig,  g_Abig);
    cudaGetSymbolAddress((void**)&pWc,    g_Wc);
    cudaGetSymbolAddress((void**)&pWg,    g_Wg);

    // smem: 3 stages * (64 + 128) rows * 40 halves * 2B = 46080
    constexpr int SMEMB = 3 * (64 + 128) * 40 * (int)sizeof(__half);
    cudaFuncSetAttribute((const void*)gemm_fp16<0>,
                         cudaFuncAttributeMaxDynamicSharedMemorySize, SMEMB);
    cudaFuncSetAttribute((const void*)gemm_fp16<1>,
                         cudaFuncAttributeMaxDynamicSharedMemorySize, SMEMB);

    // one-time stream/event creation (host resources only)
    static cudaStream_t s2 = nullptr;
    static cudaEvent_t evA = nullptr, evB = nullptr;
    if (!s2) {
        cudaStreamCreateWithFlags(&s2, cudaStreamNonBlocking);
        cudaEventCreateWithFlags(&evA, cudaEventDisableTiming);
        cudaEventCreateWithFlags(&evB, cudaEventDisableTiming);
    }

    // fork: init_weights on s2 runs concurrently with attn on the main stream
    cudaEventRecord(evA, 0);
    cudaStreamWaitEvent(s2, evA, 0);
    init_weights<<<512, 256, 0, s2>>>(Wcomb, bcomb, Wih, Whh, bih, bhh);
    attn_kernel<<<B, 256>>>(input, hidden, cell, enc, Wattn, battn, o_aw);
    // join: comb GEMM needs both attn outputs and weights
    cudaEventRecord(evB, s2);
    cudaStreamWaitEvent(0, evB, 0);

    // comb: Abig[:, 0:512] = relu(Xc @ Wc^T)  -> half into g_Abig
    {
        dim3 grid(HH / 128, B / 64);
        gemm_fp16<0><<<grid, 128, SMEMB>>>(pXc, KC, pWc, KC, pAbig, KG, KC,
                                           nullptr, nullptr, nullptr);
    }
    // gates GEMM with fused LSTM epilogue -> o_h, o_c
    {
        dim3 grid((4 * HH) / 128, B / 64);
        gemm_fp16<1><<<grid, 128, SMEMB>>>(pAbig, KG, pWg, KG, nullptr, 0, KG,
                                           cell, o_h, o_c);
    }
    dot_kernel<<<B, 512>>>(o_h, Wout, bout, o_output);
}

// round 16
// speedup vs baseline: 1.1109x; 1.1109x over previous
#include <cuda_runtime.h>
#include <cstdint>
#include <cuda_fp16.h>
#include <mma.h>
#include <math.h>

using namespace nvcuda;

#define HH 512
#define SS 6
#define MAXB 16384
#define KC 576      // comb K: 512 attn_applied + input + bias + pad to 64
#define KG 1088     // gates K: 512 x + 512 hidden + bias + pad to 64

// ---- scratch (static device globals; no runtime allocation) ----
__device__ __align__(16) __half g_Xc  [(size_t)MAXB * KC];
__device__ __align__(16) __half g_Abig[(size_t)MAXB * KG];
__device__ __align__(16) __half g_Wc  [HH * KC];
__device__ __align__(16) __half g_Wg  [4 * HH * KG];   // rows interleaved: n' = 4*j + gate

__device__ __forceinline__ float sigm_fast(float x) {
    return __fdividef(1.f, 1.f + __expf(-x));
}
__device__ __forceinline__ float tanh_fast(float x) {
    return __fmaf_rn(2.f, sigm_fast(2.f * x), -1.f);
}

// ---- build padded weight matrices (fp16) ----
// g_Wg row n' = 4*j + g  maps to torch row  n_old = g*512 + j  (gate order i,f,g,o)
__global__ void init_weights(const float* __restrict__ Wcomb, const float* __restrict__ bcomb,
                             const float* __restrict__ Wih,   const float* __restrict__ Whh,
                             const float* __restrict__ bih,   const float* __restrict__ bhh) {
    int idx = blockIdx.x * blockDim.x + threadIdx.x;
    int stride = gridDim.x * blockDim.x;
    for (int i = idx; i < HH * KC; i += stride) {
        int n = i / KC, k = i % KC;
        float v = 0.f;
        if (k < 512)        v = Wcomb[n * 513 + 1 + k];
        else if (k == 512)  v = Wcomb[n * 513];
        else if (k == 513)  v = bcomb[n];
        g_Wc[i] = __float2half_rn(v);
    }
    for (int i = idx; i < 4 * HH * KG; i += stride) {
        int np = i / KG, k = i % KG;
        int j = np >> 2, g = np & 3;
        int n = g * 512 + j;               // torch gate-major row
        float v = 0.f;
        if (k < 512)        v = Wih[n * 512 + k];
        else if (k < 1024)  v = Whh[n * 512 + (k - 512)];
        else if (k == 1024) v = bih[n] + bhh[n];
        g_Wg[i] = __float2half_rn(v);
    }
}

// ---- attention (R11 version: 256 threads, best measured) ----
__global__ void attn_kernel(const float* __restrict__ input, const float* __restrict__ hidden,
                            const float* __restrict__ cell,  const float* __restrict__ enc,
                            const float* __restrict__ Wattn, const float* __restrict__ battn,
                            float* __restrict__ out_attnw) {
    int b = blockIdx.x;
    int tid = threadIdx.x;             // 256 threads
    __shared__ float s_w[SS];
    __shared__ float s_part[8][SS];

    float h0 = hidden[(size_t)b * HH + tid];
    float h1 = hidden[(size_t)b * HH + tid + 256];
    float c0 = cell  [(size_t)b * HH + tid];
    float c1 = cell  [(size_t)b * HH + tid + 256];

    float p[SS];
#pragma unroll
    for (int s = 0; s < SS; s++) {
        const float* wr = Wattn + s * 1025;
        p[s] = wr[1 + tid] * h0 + wr[1 + tid + 256] * h1
             + wr[513 + tid] * c0 + wr[513 + tid + 256] * c1;
    }
#pragma unroll
    for (int s = 0; s < SS; s++)
#pragma unroll
        for (int off = 16; off; off >>= 1)
            p[s] += __shfl_down_sync(0xffffffffu, p[s], off);
    int warp = tid >> 5, lane = tid & 31;
    if (lane == 0)
#pragma unroll
        for (int s = 0; s < SS; s++) s_part[warp][s] = p[s];
    __syncthreads();

    if (tid == 0) {
        float inp = input[b];
        float lg[SS], mx = -1e30f;
#pragma unroll
        for (int s = 0; s < SS; s++) {
            float v = battn[s] + Wattn[s * 1025] * inp;
#pragma unroll
            for (int w = 0; w < 8; w++) v += s_part[w][s];
            lg[s] = v; mx = fmaxf(mx, v);
        }
        float sum = 0.f;
#pragma unroll
        for (int s = 0; s < SS; s++) { lg[s] = __expf(lg[s] - mx); sum += lg[s]; }
        float inv = __fdividef(1.f, sum);
#pragma unroll
        for (int s = 0; s < SS; s++) {
            float w = lg[s] * inv;
            s_w[s] = w;
            out_attnw[(size_t)b * SS + s] = w;
        }
    }
    __syncthreads();

    float w0 = s_w[0], w1 = s_w[1], w2 = s_w[2], w3 = s_w[3], w4 = s_w[4], w5 = s_w[5];
    const float* eb = enc + (size_t)b * SS * HH;
#pragma unroll
    for (int r = 0; r < 2; r++) {
        int k = tid + r * 256;
        float a = w0 * eb[k]          + w1 * eb[HH + k]     + w2 * eb[2 * HH + k]
                + w3 * eb[3 * HH + k] + w4 * eb[4 * HH + k] + w5 * eb[5 * HH + k];
        g_Xc[(size_t)b * KC + k] = __float2half_rn(a);
        g_Abig[(size_t)b * KG + 512 + k] = __float2half_rn((r == 0) ? h0 : h1);
    }
    if (tid < 64) {
        float v = 0.f;
        if (tid == 0) v = input[b];
        else if (tid == 1) v = 1.f;
        g_Xc[(size_t)b * KC + 512 + tid] = __float2half_rn(v);
        float u = (tid == 0) ? 1.f : 0.f;
        g_Abig[(size_t)b * KG + 1024 + tid] = __float2half_rn(u);
    }
}

// ---- fp16 wmma GEMM, 64x128 CTA tile, 4 warps (32x64/warp), BK=64,
//      2-stage cp.async, 4 CTAs/SM (R14 winning config) ----
// EPI 0: relu -> half C  (comb)   EPI 1: fused LSTM (gates; N interleaved 4*j+g)
#define CP16(dst_u32, src_ptr) \
    asm volatile("cp.async.cg.shared.global [%0], [%1], 16;" :: "r"(dst_u32), "l"(src_ptr))

template <int EPI>
__global__ void __launch_bounds__(128, 4)
gemm_fp16(const __half* __restrict__ A, int lda,
          const __half* __restrict__ Bw, int ldb,
          void* __restrict__ Cv, int ldc, int K,
          const float* __restrict__ cell,
          float* __restrict__ o_h, float* __restrict__ o_c) {
    constexpr int BM = 64, BN = 128, BK = 64, PAD = 72;   // PAD halves (144B rows)
    extern __shared__ __half smem[];
    __half* As = smem;                      // 2 stages * BM*PAD
    __half* Bs = smem + 2 * BM * PAD;       // 2 stages * BN*PAD

    int m0 = blockIdx.y * BM, n0 = blockIdx.x * BN;
    int tid = threadIdx.x;                  // 128 threads = 4 warps
    int warp = tid >> 5, lane = tid & 31;
    int wr = warp & 1;    // 0..1 -> 32-row slab
    int wc = warp >> 1;   // 0..1 -> 64-col slab

    wmma::fragment<wmma::accumulator, 16, 16, 16, float> acc[2][4];
#pragma unroll
    for (int i = 0; i < 2; i++)
#pragma unroll
        for (int j = 0; j < 4; j++) wmma::fill_fragment(acc[i][j], 0.f);

    int nk = K / BK;

    auto stage_copy = [&](int st, int k0) {
#pragma unroll
        for (int i = 0; i < 4; i++) {       // A: 64 rows x 8 chunks = 512
            int q = tid + i * 128;
            int row = q >> 3, c8 = (q & 7) << 3;
            const __half* ga = &A[(size_t)(m0 + row) * lda + k0 + c8];
            unsigned int sa = (unsigned int)__cvta_generic_to_shared(&As[st * BM * PAD + row * PAD + c8]);
            CP16(sa, ga);
        }
#pragma unroll
        for (int i = 0; i < 8; i++) {       // B: 128 rows x 8 chunks = 1024
            int q = tid + i * 128;
            int row = q >> 3, c8 = (q & 7) << 3;
            const __half* gb = &Bw[(size_t)(n0 + row) * ldb + k0 + c8];
            unsigned int sb = (unsigned int)__cvta_generic_to_shared(&Bs[st * BN * PAD + row * PAD + c8]);
            CP16(sb, gb);
        }
        asm volatile("cp.async.commit_group;");
    };

    stage_copy(0, 0);

    for (int t = 0; t < nk; t++) {
        asm volatile("cp.async.wait_group 0;");
        __syncthreads();   // stage t visible; stage t-1 consumed -> buffer free
        if (t + 1 < nk) stage_copy((t + 1) & 1, (t + 1) * BK);

        const __half* Ab = &As[(t & 1) * BM * PAD];
        const __half* Bb = &Bs[(t & 1) * BN * PAD];

#pragma unroll
        for (int kk = 0; kk < 4; kk++) {     // 4 x k=16
            wmma::fragment<wmma::matrix_a, 16, 16, 16, __half, wmma::row_major> af[2];
            wmma::fragment<wmma::matrix_b, 16, 16, 16, __half, wmma::col_major> bf[4];
#pragma unroll
            for (int i = 0; i < 2; i++)
                wmma::load_matrix_sync(af[i], &Ab[(wr * 32 + i * 16) * PAD + kk * 16], PAD);
#pragma unroll
            for (int j = 0; j < 4; j++)
                wmma::load_matrix_sync(bf[j], &Bb[(wc * 64 + j * 16) * PAD + kk * 16], PAD);
#pragma unroll
            for (int i = 0; i < 2; i++)
#pragma unroll
                for (int j = 0; j < 4; j++)
                    wmma::mma_sync(acc[i][j], af[i], bf[j], acc[i][j]);
        }
    }

    // ---- epilogue: stage accumulators through smem ----
    __syncthreads();                      // mainloop smem dead, reuse as f32 staging
    float* stg = (float*)smem;
    constexpr int LDS_ = 68;
    float* wbase = stg + warp * 32 * LDS_;   // 32 rows x 68 f32 per warp
#pragma unroll
    for (int i = 0; i < 2; i++)
#pragma unroll
        for (int j = 0; j < 4; j++)
            wmma::store_matrix_sync(&wbase[(i * 16) * LDS_ + j * 16], acc[i][j],
                                    LDS_, wmma::mem_row_major);
    __syncwarp();

    if (EPI == 0) {
        __half* Ch = (__half*)Cv;
        {
            int r = lane;                 // 32 lanes cover the 32 rows
            size_t grow = (size_t)(m0 + wr * 32 + r) * ldc + n0 + wc * 64;
#pragma unroll
            for (int c = 0; c < 64; c += 2) {
                float x = fmaxf(wbase[r * LDS_ + c], 0.f);
                float y = fmaxf(wbase[r * LDS_ + c + 1], 0.f);
                *(__half2*)&Ch[grow + c] = __floats2half2_rn(x, y);
            }
        }
    } else {
        // fused LSTM: this warp's 64 cols = interleaved gates for 16 hidden units
        int nbase = n0 + wc * 64;
        int jbase = nbase >> 2;
#pragma unroll 4
        for (int it = 0; it < 16; it++) {
            int idx = it * 32 + lane;         // 0..511 over (row, jj)
            int r = idx >> 4, jj = idx & 15;
            int b = m0 + wr * 32 + r;
            int j = jbase + jj;
            const float* cellrow = &wbase[r * LDS_ + jj * 4];
            float gi = cellrow[0], gf = cellrow[1], gg = cellrow[2], go = cellrow[3];
            float c_old = cell[(size_t)b * HH + j];
            float si = sigm_fast(gi);
            float sf = sigm_fast(gf);
            float so = sigm_fast(go);
            float tg = tanh_fast(gg);
            float cn = sf * c_old + si * tg;
            float hn = so * tanh_fast(cn);
            o_c[(size_t)b * HH + j] = cn;
            o_h[(size_t)b * HH + j] = hn;
        }
    }
}

// ---- output dot: out[b] = dot(o_h[b,:], Wout) + bout ----
__global__ void dot_kernel(const float* __restrict__ o_h, const float* __restrict__ Wout,
                           const float* __restrict__ bout, float* __restrict__ out_output) {
    int b = blockIdx.x, j = threadIdx.x;   // 512 threads
    float part = o_h[(size_t)b * HH + j] * Wout[j];
#pragma unroll
    for (int off = 16; off; off >>= 1) part += __shfl_down_sync(0xffffffffu, part, off);
    __shared__ float sp[16];
    if ((j & 31) == 0) sp[j >> 5] = part;
    __syncthreads();
    if (j < 16) {
        float v = sp[j];
#pragma unroll
        for (int off = 8; off; off >>= 1) v += __shfl_down_sync(0xffffu, v, off);
        if (j == 0) out_output[b] = v + bout[0];
    }
}

extern "C" void kernel_launch(void* const* d_in, const int* in_sizes, int n_in,
                              void* d_out, int out_size) {
    const float* input  = (const float*)d_in[0];
    const float* hidden = (const float*)d_in[1];
    const float* cell   = (const float*)d_in[2];
    const float* enc    = (const float*)d_in[3];
    const float* Wattn  = (const float*)d_in[4];
    const float* battn  = (const float*)d_in[5];
    const float* Wcomb  = (const float*)d_in[6];
    const float* bcomb  = (const float*)d_in[7];
    const float* Wih    = (const float*)d_in[8];
    const float* Whh    = (const float*)d_in[9];
    const float* bih    = (const float*)d_in[10];
    const float* bhh    = (const float*)d_in[11];
    const float* Wout   = (const float*)d_in[12];
    const float* bout   = (const float*)d_in[13];

    int B = in_sizes[1] / HH;   // 16384

    float* out      = (float*)d_out;
    float* o_output = out;                              // [B, 1]
    float* o_h      = out + (size_t)B;                  // [B, H]
    float* o_c      = o_h + (size_t)B * HH;             // [B, H]
    float* o_aw     = o_c + (size_t)B * HH;             // [B, 1, S]

    __half *pXc, *pAbig, *pWc, *pWg;
    cudaGetSymbolAddress((void**)&pXc,    g_Xc);
    cudaGetSymbolAddress((void**)&pAbig,  g_Abig);
    cudaGetSymbolAddress((void**)&pWc,    g_Wc);
    cudaGetSymbolAddress((void**)&pWg,    g_Wg);

    // smem: 2 stages * (64 + 128) rows * 72 halves * 2B = 55296
    constexpr int SMEMB = 2 * (64 + 128) * 72 * (int)sizeof(__half);
    cudaFuncSetAttribute((const void*)gemm_fp16<0>,
                         cudaFuncAttributeMaxDynamicSharedMemorySize, SMEMB);
    cudaFuncSetAttribute((const void*)gemm_fp16<1>,
                         cudaFuncAttributeMaxDynamicSharedMemorySize, SMEMB);

    // one-time stream/event creation (host resources only)
    static cudaStream_t s2 = nullptr;
    static cudaEvent_t evA = nullptr, evB = nullptr;
    if (!s2) {
        cudaStreamCreateWithFlags(&s2, cudaStreamNonBlocking);
        cudaEventCreateWithFlags(&evA, cudaEventDisableTiming);
        cudaEventCreateWithFlags(&evB, cudaEventDisableTiming);
    }

    // fork: init_weights on s2 runs concurrently with attn on the main stream
    cudaEventRecord(evA, 0);
    cudaStreamWaitEvent(s2, evA, 0);
    init_weights<<<512, 256, 0, s2>>>(Wcomb, bcomb, Wih, Whh, bih, bhh);
    attn_kernel<<<B, 256>>>(input, hidden, cell, enc, Wattn, battn, o_aw);
    // join: comb GEMM needs both attn outputs and weights
    cudaEventRecord(evB, s2);
    cudaStreamWaitEvent(0, evB, 0);

    // comb: Abig[:, 0:512] = relu(Xc @ Wc^T)  -> half into g_Abig
    {
        dim3 grid(HH / 128, B / 64);
        gemm_fp16<0><<<grid, 128, SMEMB>>>(pXc, KC, pWc, KC, pAbig, KG, KC,
                                           nullptr, nullptr, nullptr);
    }
    // gates GEMM with fused LSTM epilogue -> o_h, o_c
    {
        dim3 grid((4 * HH) / 128, B / 64);
        gemm_fp16<1><<<grid, 128, SMEMB>>>(pAbig, KG, pWg, KG, nullptr, 0, KG,
                                           cell, o_h, o_c);
    }
    dot_kernel<<<B, 512>>>(o_h, Wout, bout, o_output);
}